// round 2
// baseline (speedup 1.0000x reference)
#include <cuda_runtime.h>
#include <stdint.h>

#define OF 28672
#define IF 8192
#define NG 256      // groups of 32 inputs
#define JW 36       // padded x' entries per group (34 used)

__device__ float g_xs[NG * JW];
__device__ float g_sumx;

// Prep: block 0 reduces sum(x); blocks 1.. build the pre-scaled x' table.
__global__ void prep_kernel(const float* __restrict__ x) {
    int t = threadIdx.x;
    if (blockIdx.x == 0) {
        __shared__ float red[256];
        float s = 0.f;
        for (int i = t; i < IF; i += 256) s += x[i];
        red[t] = s;
        __syncthreads();
        #pragma unroll
        for (int off = 128; off > 0; off >>= 1) {
            if (t < off) red[t] += red[t + off];
            __syncthreads();
        }
        if (t == 0) g_sumx = red[0];
    } else {
        int e = (blockIdx.x - 1) * 256 + t;
        if (e < NG * JW) {
            int g = e / JW, j = e % JW;
            float v = 0.f;
            if (j < 34) {
                int xoff, se;
                if (j < 10)       { xoff = j;                      se = -3 * j;        }
                else if (j == 10) { xoff = 10;                     se = -30;           }
                else if (j == 11) { xoff = 10;                     se = 2;             }
                else if (j < 22)  { int k = j - 12; xoff = 11 + k; se = -(3 * k + 1);  }
                else if (j == 22) { xoff = 21;                     se = -31;           }
                else if (j == 23) { xoff = 21;                     se = 1;             }
                else              { int k = j - 24; xoff = 22 + k; se = -(3 * k + 2);  }
                v = ldexpf(x[g * 32 + xoff], se);
            }
            g_xs[e] = v;
        }
    }
}

// Main GEMV: CTA = 32 columns x 8 K-slices. Each thread: 1 column, 32 groups
// (96 qweight rows). Per 3-bit code: LOP3 (mask) + I2F (exact) + FFMA with
// pre-scaled x'. Split codes handled as two masked terms.
__global__ void __launch_bounds__(256, 3) gemv3_kernel(
    const uint32_t* __restrict__ qw,
    const float* __restrict__ scales,
    const float* __restrict__ zeros,
    const float* __restrict__ bias,
    float* __restrict__ out)
{
    __shared__ float smx[NG * JW];
    __shared__ float part[256];
    const int t = threadIdx.x;

    // Stage x' table into SMEM (36 KB), vectorized.
    {
        const float4* src = (const float4*)g_xs;
        float4* dst = (float4*)smx;
        #pragma unroll
        for (int i = 0; i < (NG * JW / 4) / 256; i++)
            dst[t + 256 * i] = src[t + 256 * i];
    }
    __syncthreads();

    const int lane = t & 31;
    const int sl   = t >> 5;                 // K-slice 0..7
    const int col  = blockIdx.x * 32 + lane; // coalesced across warp
    const uint32_t* p = qw + (size_t)(96 * sl) * OF + col;

    float a[4] = {0.f, 0.f, 0.f, 0.f};

    #pragma unroll 2
    for (int g = 0; g < 32; g++) {
        uint32_t w0 = p[0];
        uint32_t w1 = p[OF];
        uint32_t w2 = p[2 * OF];
        p += 3 * OF;

        float xv[JW];
        const float4* xs = (const float4*)(smx + (sl * 32 + g) * JW);
        #pragma unroll
        for (int q = 0; q < JW / 4; q++)
            *(float4*)(xv + 4 * q) = xs[q];

        int rr = 0;
        #define ACCUM(M, XI) { a[rr & 3] = fmaf(__uint2float_rn(M), xv[XI], a[rr & 3]); rr++; }
        #pragma unroll
        for (int k = 0; k < 10; k++) ACCUM(w0 & (7u << (3 * k)), k);
        ACCUM(w0 & 0xC0000000u, 10);          // low 2 bits of code 10 (scale 2^-30)
        ACCUM(w1 & 1u,          11);          // high bit of code 10 (scale 2^2)
        #pragma unroll
        for (int k = 0; k < 10; k++) ACCUM(w1 & (7u << (3 * k + 1)), 12 + k);
        ACCUM(w1 & 0x80000000u, 22);          // low bit of code 21 (scale 2^-31)
        ACCUM(w2 & 3u,          23);          // high 2 bits of code 21 (scale 2^1)
        #pragma unroll
        for (int k = 0; k < 10; k++) ACCUM(w2 & (7u << (3 * k + 2)), 24 + k);
        #undef ACCUM
    }

    part[t] = (a[0] + a[1]) + (a[2] + a[3]);
    __syncthreads();

    if (t < 32) {
        float dot = 0.f;
        #pragma unroll
        for (int k = 0; k < 8; k++) dot += part[t + 32 * k];
        const int c = blockIdx.x * 32 + t;
        out[c] = fmaf(scales[c], dot, fmaf(-zeros[c], g_sumx, bias[c]));
    }
}

extern "C" void kernel_launch(void* const* d_in, const int* in_sizes, int n_in,
                              void* d_out, int out_size) {
    const float*    x      = (const float*)d_in[0];
    const uint32_t* qw     = (const uint32_t*)d_in[1];
    const float*    scales = (const float*)d_in[2];
    const float*    zeros  = (const float*)d_in[3];
    const float*    bias   = (const float*)d_in[4];
    float*          out    = (float*)d_out;

    prep_kernel<<<1 + (NG * JW + 255) / 256, 256>>>(x);
    gemv3_kernel<<<OF / 32, 256>>>(qw, scales, zeros, bias, out);
}